// round 16
// baseline (speedup 1.0000x reference)
#include <cuda_runtime.h>
#include <math.h>

#define VSZ 30000
#define DM  640
#define NL  6
#define NH  8
#define DHD 80
#define FFH 2560
#define BB  4
#define SSQ 33
#define EOS_TOK 2
#define NBLK 148
#define NTHR 512
#define NWP  16
#define TOTW (NBLK*NWP)
#define KS   32               // k-slices per block
#define CW   16               // chunk width (columns)

struct Params {
    const int* words;
    const float *emb,*Wq,*bq,*Wk,*bk,*Wv,*bv,*Wo,*bo;
    const float *ln1s,*ln1b,*W1,*b1,*W2,*b2,*ln2s,*ln2b,*lmW,*lmb;
    float* out;
};

// ------------------------- device state -------------------------
__device__ unsigned g_bar_count;
__device__ unsigned g_bar_gen;
__device__ int g_stop;
__device__ int g_inp[BB*SSQ];
__device__ unsigned long long g_best[BB];
__device__ float g_h [36*DM];
__device__ float g_h2[36*DM];
__device__ float g_q [36*DM];
__device__ float g_ao[36*DM];
__device__ float g_r1[36*DM];
__device__ float g_f1[36*FFH];
__device__ float g_r2[36*DM];
__device__ float g_kc[NL*BB*SSQ*DM];
__device__ float g_vc[NL*BB*SSQ*DM];

struct Shr {
    const float* rpE[36];
    const float* rpH[36];
    const float* rpH2[36];
    const float* rpAO[36];
    const float* rpF1[36];
    const float* rpLM[4];
    unsigned long long sk[64];
    float s[4*NTHR];          // split-K reduction buffer (8KB)
};

// ------------------------- grid barrier -------------------------
// arrivals: one atomicAdd per block; waiters: volatile L2 reads (no atomic contention)
__device__ __forceinline__ void gsync(unsigned &gen) {
    __syncthreads();
    if (threadIdx.x == 0) {
        __threadfence();
        unsigned arrived = atomicAdd(&g_bar_count, 1u);
        if (arrived == NBLK - 1u) {
            g_bar_count = 0u;
            __threadfence();
            atomicAdd(&g_bar_gen, 1u);
        } else {
            while (*(volatile unsigned*)&g_bar_gen == gen) __nanosleep(32);
        }
        __threadfence();
    }
    gen++;
    __syncthreads();
}

// ------------------------- 4-row x 16-col tile, 32-way split-K -------------------------
// thread t: c = t&15 (column), ks = t>>4 (k-slice). Warp = 2 x 64B contiguous W rows.
__device__ __forceinline__ void tile_dot4(const float* const* rowp, int row0,
                                          const float* __restrict__ W, int N, int KL,
                                          int n, float acc[4]) {
    const int ks = threadIdx.x >> 4;
    const float* a0 = rowp[row0+0] + ks*KL;
    const float* a1 = rowp[row0+1] + ks*KL;
    const float* a2 = rowp[row0+2] + ks*KL;
    const float* a3 = rowp[row0+3] + ks*KL;
    acc[0] = acc[1] = acc[2] = acc[3] = 0.f;
    const float* Wp = W + (long long)(ks*KL)*N + n;
#pragma unroll 4
    for (int kk = 0; kk < KL; kk++) {
        float w = __ldg(Wp); Wp += N;
        acc[0] = fmaf(a0[kk], w, acc[0]);
        acc[1] = fmaf(a1[kk], w, acc[1]);
        acc[2] = fmaf(a2[kk], w, acc[2]);
        acc[3] = fmaf(a3[kk], w, acc[3]);
    }
}

// reduce 32 k-slices; threads t<64 own (m=t>>4, col=t&15)
__device__ __forceinline__ float tile_reduce4(float acc[4], float* s, int& m, int& c) {
    const int t = threadIdx.x;
    __syncthreads();
#pragma unroll
    for (int mm = 0; mm < 4; mm++) s[mm*NTHR + t] = acc[mm];
    __syncthreads();
    if (t >= 64) { m = 0; c = -1; return 0.f; }
    m = t >> 4; c = t & 15;
    float v = 0.f;
#pragma unroll
    for (int q = 0; q < KS; q++) v += s[m*NTHR + q*CW + c];
    return v;
}

// ------------------------- generic GEMM phase -------------------------
template<int M, bool RELU>
__device__ void gemm_phase(const float* const* rowp, const float* __restrict__ W,
                           const float* __restrict__ bias, float* out,
                           int K, int N, float* s) {
    const int KL = K / KS;
    const int nch = N / CW;
    for (int ch = blockIdx.x; ch < nch; ch += NBLK) {
        int n0 = ch * CW;
        for (int t0 = 0; t0 < M; t0 += 4) {
            float acc[4];
            tile_dot4(rowp, t0, W, N, KL, n0 + (threadIdx.x & 15), acc);
            int m, c;
            float v = tile_reduce4(acc, s, m, c);
            if (c >= 0) {
                int n = n0 + c;
                v += __ldg(bias + n);
                if (RELU) v = fmaxf(v, 0.f);
                out[(t0 + m)*N + n] = v;
            }
        }
    }
}

// ------------------------- QKV phase -------------------------
template<int NC>
__device__ void qkv_phase(const Params& P, int l, int p0,
                          const float* const* rowp, float* s) {
    constexpr int M = 4*NC;
    const int KL = DM / KS;              // 20
    const int CPM = DM / CW;             // 40
    for (int ch = blockIdx.x; ch < 3*CPM; ch += NBLK) {
        int sel = ch / CPM;
        int n0 = (ch - sel*CPM) * CW;
        const float* W    = ((sel==0) ? P.Wq : (sel==1) ? P.Wk : P.Wv) + (long long)l*DM*DM;
        const float* bias = ((sel==0) ? P.bq : (sel==1) ? P.bk : P.bv) + l*DM;
        for (int t0 = 0; t0 < M; t0 += 4) {
            float acc[4];
            tile_dot4(rowp, t0, W, DM, KL, n0 + (threadIdx.x & 15), acc);
            int m, c;
            float v = tile_reduce4(acc, s, m, c);
            if (c >= 0) {
                int n = n0 + c;
                v += __ldg(bias + n);
                int mg = t0 + m;
                int b = mg / NC, jj = mg - b*NC, p = p0 + jj;
                if (sel == 0)      g_q[mg*DM + n] = v;
                else if (sel == 1) g_kc[((l*BB + b)*SSQ + p)*DM + n] = v;
                else               g_vc[((l*BB + b)*SSQ + p)*DM + n] = v;
            }
        }
    }
}

// ------------------------- LM head + argmax phase -------------------------
__device__ void lm_phase(const Params& P, const float* const* rowp,
                         float* s, unsigned long long* sk) {
    const int t = threadIdx.x;
    const int KL = DM / KS;              // 20
    const int nch = VSZ / CW;            // 1875
    unsigned long long rb = 0ull;
    for (int ch = blockIdx.x; ch < nch; ch += NBLK) {
        int n0 = ch * CW;
        float acc[4];
        tile_dot4(rowp, 0, P.lmW, VSZ, KL, n0 + (t & 15), acc);
        int m, c;
        float v = tile_reduce4(acc, s, m, c);
        if (c >= 0) {
            int n = n0 + c;
            v += __ldg(P.lmb + n);
            unsigned u = __float_as_uint(v);
            u = (u & 0x80000000u) ? ~u : (u | 0x80000000u);
            unsigned long long key =
                ((unsigned long long)u << 32) | (unsigned)(0xFFFFFFFFu - (unsigned)n);
            if (key > rb) rb = key;          // thread's m (=batch) fixed across chunks
        }
    }
    __syncthreads();
    if (t < 64) sk[t] = rb;
    __syncthreads();
    if (t < 4) {
        unsigned long long bb = sk[t*16];
        for (int i = 1; i < 16; i++) if (sk[t*16 + i] > bb) bb = sk[t*16 + i];
        if (bb) atomicMax(&g_best[t], bb);
    }
    __syncthreads();
}

// ------------------------- attention phase -------------------------
template<int NC>
__device__ void attn_phase(int l, int p0) {
    const int wp = threadIdx.x >> 5, lane = threadIdx.x & 31;
    const int total = BB*NH*NC;
    for (int tup = blockIdx.x*NWP + wp; tup < total; tup += TOTW) {
        int b = tup / (NH*NC);
        int rem = tup - b*NH*NC;
        int h = rem / NC, j = rem - h*NC;
        int p = p0 + j, nk = p + 1;
        int r = b*NC + j;
        float* qp = g_q + r*DM + h*DHD;
        float sc = -1e30f;
        if (lane < nk) {
            float* kp = g_kc + ((l*BB + b)*SSQ + lane)*DM + h*DHD;
            float sv = 0.f;
#pragma unroll
            for (int d = 0; d < DHD; d++) sv = fmaf(qp[d], kp[d], sv);
            sc = sv / sqrtf((float)DHD);
        }
        float mx = sc;
        for (int o = 16; o > 0; o >>= 1) mx = fmaxf(mx, __shfl_xor_sync(0xffffffffu, mx, o));
        float e = (lane < nk) ? expf(sc - mx) : 0.f;
        float sum = e;
        for (int o = 16; o > 0; o >>= 1) sum += __shfl_xor_sync(0xffffffffu, sum, o);
        float o0 = 0.f, o1 = 0.f, o2 = 0.f;
        float* vb = g_vc + ((l*BB + b)*SSQ)*DM + h*DHD;
        for (int jk = 0; jk < nk; jk++) {
            float pj = __shfl_sync(0xffffffffu, e, jk) / sum;
            float* vp = vb + jk*DM;
            o0 = fmaf(pj, vp[lane],      o0);
            o1 = fmaf(pj, vp[lane + 32], o1);
            if (lane < 16) o2 = fmaf(pj, vp[lane + 64], o2);
        }
        float* ao = g_ao + r*DM + h*DHD;
        ao[lane] = o0; ao[lane + 32] = o1;
        if (lane < 16) ao[lane + 64] = o2;
    }
}

// ------------------------- LayerNorm phase -------------------------
__device__ __forceinline__ void ln_row_warp(const float* a, const float* r,
                                            const float* __restrict__ sc,
                                            const float* __restrict__ bi,
                                            float* dst) {
    int lane = threadIdx.x & 31;
    float v[20];
    float sum = 0.f;
#pragma unroll
    for (int i = 0; i < 20; i++) {
        float x = a[lane + 32*i] + r[lane + 32*i];
        v[i] = x; sum += x;
    }
#pragma unroll
    for (int o = 16; o > 0; o >>= 1) sum += __shfl_xor_sync(0xffffffffu, sum, o);
    float mean = sum / DM;
    float vs = 0.f;
#pragma unroll
    for (int i = 0; i < 20; i++) { float d = v[i] - mean; vs += d*d; }
#pragma unroll
    for (int o = 16; o > 0; o >>= 1) vs += __shfl_xor_sync(0xffffffffu, vs, o);
    float dn = sqrtf(vs / DM + 1e-6f);
#pragma unroll
    for (int i = 0; i < 20; i++)
        dst[lane + 32*i] = (v[i] - mean) / dn * __ldg(sc + lane + 32*i)
                           + __ldg(bi + lane + 32*i);
}

template<int M>
__device__ void ln_phase(const float* a, const float* r,
                         const float* __restrict__ sc, const float* __restrict__ bi,
                         float* dst) {
    int gw = blockIdx.x*NWP + (threadIdx.x >> 5);
    for (int row = gw; row < M; row += TOTW)
        ln_row_warp(a + row*DM, r + row*DM, sc, bi, dst + row*DM);
}

// ------------------------- one generation step -------------------------
template<int NC>
__device__ void do_step(int p0, int cl, const Params& P, unsigned &gen, Shr& S) {
    constexpr int M = 4*NC;
    const int t = threadIdx.x;
    if (t < M) {
        int b = t / NC, j = t - b*NC;
        int tok = g_inp[b*SSQ + p0 + j];
        if (tok < 0 || tok >= VSZ) tok = 0;
        S.rpE [t] = P.emb + (long long)tok * DM;
        S.rpH [t] = g_h  + t*DM;
        S.rpH2[t] = g_h2 + t*DM;
        S.rpAO[t] = g_ao + t*DM;
        S.rpF1[t] = g_f1 + t*FFH;
    }
    if (t < 4) S.rpLM[t] = g_h + ((t+1)*NC - 1)*DM;
    __syncthreads();

    // materialize g_h = embeddings (residual for LN1 of layer 0), striped by block
    for (int r = blockIdx.x; r < M; r += NBLK)
        for (int d = t; d < DM; d += NTHR)
            g_h[r*DM + d] = __ldg(S.rpE[r] + d);

    for (int l = 0; l < NL; l++) {
        qkv_phase<NC>(P, l, p0, (l == 0) ? S.rpE : S.rpH, S.s);               gsync(gen);
        attn_phase<NC>(l, p0);                                                gsync(gen);
        gemm_phase<M,false>(S.rpAO, P.Wo + (long long)l*DM*DM,
                            P.bo + l*DM, g_r1, DM, DM, S.s);                  gsync(gen);
        ln_phase<M>(g_h, g_r1, P.ln1s + l*DM, P.ln1b + l*DM, g_h2);           gsync(gen);
        gemm_phase<M,true >(S.rpH2, P.W1 + (long long)l*DM*FFH,
                            P.b1 + l*FFH, g_f1, DM, FFH, S.s);                gsync(gen);
        gemm_phase<M,false>(S.rpF1, P.W2 + (long long)l*FFH*DM,
                            P.b2 + l*DM, g_r2, FFH, DM, S.s);                 gsync(gen);
        ln_phase<M>(g_h2, g_r2, P.ln2s + l*DM, P.ln2b + l*DM, g_h);           gsync(gen);
    }
    lm_phase(P, S.rpLM, S.s, S.sk);                                           gsync(gen);
    if (blockIdx.x == 0 && threadIdx.x == 0) {
        bool alleos = true;
        for (int b = 0; b < BB; b++) {
            int tok = (int)(0xFFFFFFFFu - (unsigned)(g_best[b] & 0xFFFFFFFFu));
            g_inp[b*SSQ + cl + 1] = tok;
            P.out[b*32 + cl] = (float)tok;
            if (tok != EOS_TOK) alleos = false;
            g_best[b] = 0ull;
        }
        if (alleos) g_stop = 1;
    }
    gsync(gen);
}

// ------------------------- persistent mega-kernel -------------------------
__global__ __launch_bounds__(NTHR, 1)
void mega_kernel(Params P) {
    __shared__ Shr S;
    __shared__ unsigned s_gen;
    if (threadIdx.x == 0) s_gen = atomicAdd(&g_bar_gen, 0u);
    __syncthreads();
    unsigned gen = s_gen;

    if (blockIdx.x == 0) {
        int t = threadIdx.x;
        if (t < BB*SSQ) g_inp[t] = 0;
        if (t < BB*32)  P.out[t] = 0.f;
        __syncthreads();
        if (t == 0) g_stop = 0;
        if (t < BB) { g_inp[t*SSQ] = 1; g_best[t] = 0ull; }
        if (t < 32) {
            int tok = P.words[t];
            g_inp[(t >> 3)*SSQ + 1 + (t & 7)] = tok;
            P.out[(t >> 3)*32 + (t & 7)] = (float)tok;
        }
    }
    gsync(gen);

    do_step<9>(0, 8, P, gen, S);                 // prefill -> token at col 8
    for (int p = 9; p <= 31; p++) {
        if (*(volatile int*)&g_stop) break;      // uniform post-barrier
        do_step<1>(p, p, P, gen, S);
    }
}

// ------------------------- host -------------------------
extern "C" void kernel_launch(void* const* d_in, const int* in_sizes, int n_in,
                              void* d_out, int out_size) {
    (void)in_sizes; (void)out_size;
    int base = n_in - 19;
    Params P;
    P.words = (const int*)d_in[0];
    P.emb  = (const float*)d_in[base + 0];
    P.Wq   = (const float*)d_in[base + 1];
    P.bq   = (const float*)d_in[base + 2];
    P.Wk   = (const float*)d_in[base + 3];
    P.bk   = (const float*)d_in[base + 4];
    P.Wv   = (const float*)d_in[base + 5];
    P.bv   = (const float*)d_in[base + 6];
    P.Wo   = (const float*)d_in[base + 7];
    P.bo   = (const float*)d_in[base + 8];
    P.ln1s = (const float*)d_in[base + 9];
    P.ln1b = (const float*)d_in[base + 10];
    P.W1   = (const float*)d_in[base + 11];
    P.b1   = (const float*)d_in[base + 12];
    P.W2   = (const float*)d_in[base + 13];
    P.b2   = (const float*)d_in[base + 14];
    P.ln2s = (const float*)d_in[base + 15];
    P.ln2b = (const float*)d_in[base + 16];
    P.lmW  = (const float*)d_in[base + 17];
    P.lmb  = (const float*)d_in[base + 18];
    P.out  = (float*)d_out;

    mega_kernel<<<NBLK, NTHR>>>(P);
}

// round 17
// speedup vs baseline: 1.2912x; 1.2912x over previous
#include <cuda_runtime.h>
#include <math.h>

#define VSZ 30000
#define DM  640
#define NL  6
#define NH  8
#define DHD 80
#define FFH 2560
#define BB  4
#define SSQ 33
#define EOS_TOK 2
#define NBLK 148
#define NTHR 512
#define NWP  16
#define TOTW (NBLK*NWP)
#define KS   32
#define CW   16

struct Params {
    const int* words;
    const float *emb,*Wq,*bq,*Wk,*bk,*Wv,*bv,*Wo,*bo;
    const float *ln1s,*ln1b,*W1,*b1,*W2,*b2,*ln2s,*ln2b,*lmW,*lmb;
    float* out;
};

// ------------------------- device state -------------------------
__device__ unsigned g_gcnt[8];
__device__ unsigned g_rcnt;
__device__ volatile unsigned g_genv;
__device__ int g_inp[BB*SSQ];
__device__ unsigned long long g_bestA[SSQ][BB];   // per-step argmax keys
__device__ float g_h [36*DM];
__device__ float g_h2[36*DM];
__device__ float g_q [36*DM];
__device__ float g_ao[36*DM];
__device__ float g_r1[36*DM];
__device__ float g_f1[36*FFH];
__device__ float g_r2[36*DM];
__device__ float g_kc[NL*BB*SSQ*DM];
__device__ float g_vc[NL*BB*SSQ*DM];

struct Shr {
    const float* rp[36];
    float sA[4*DM];            // decode LN/input staging (10KB)
    float s[4*NTHR];           // split-K reduce (8KB)
    unsigned long long sk[64];
    int toks[36];
};

// ------------------------- tree grid barrier -------------------------
// arrivals: 8 self-wrapping group counters -> root; release: volatile gen write.
__device__ __forceinline__ void gsync(unsigned &gen) {
    __syncthreads();
    if (threadIdx.x == 0) {
        __threadfence();
        int g = blockIdx.x & 7;
        unsigned gsz = (g < 4) ? 19u : 18u;       // 148 = 4*19 + 4*18
        if (atomicInc(&g_gcnt[g], gsz - 1u) == gsz - 1u) {
            if (atomicInc(&g_rcnt, 7u) == 7u) {
                __threadfence();
                g_genv = gen + 1u;
            }
        }
        while (g_genv == gen) __nanosleep(32);
        __threadfence();
    }
    gen++;
    __syncthreads();
}

// ------------------------- 4-row x 16-col tile, 32-way split-K, full unroll ----------
template<int KL>
__device__ __forceinline__ void tile_dot4(const float* const* rp, int row0,
                                          const float* __restrict__ W, int N,
                                          int n, float acc[4]) {
    const int ks = threadIdx.x >> 4;
    const float* a0 = rp[row0+0] + ks*KL;
    const float* a1 = rp[row0+1] + ks*KL;
    const float* a2 = rp[row0+2] + ks*KL;
    const float* a3 = rp[row0+3] + ks*KL;
    const float* Wp = W + (long long)(ks*KL)*N + n;
    acc[0] = acc[1] = acc[2] = acc[3] = 0.f;
#pragma unroll 20
    for (int kk = 0; kk < KL; kk++) {
        float w = __ldg(Wp); Wp += N;
        acc[0] = fmaf(a0[kk], w, acc[0]);
        acc[1] = fmaf(a1[kk], w, acc[1]);
        acc[2] = fmaf(a2[kk], w, acc[2]);
        acc[3] = fmaf(a3[kk], w, acc[3]);
    }
}

// reduce 32 k-slices; threads t<64 own (m=t>>4, c=t&15)
__device__ __forceinline__ float tile_reduce4(float acc[4], float* s, int& m, int& c) {
    const int t = threadIdx.x;
    __syncthreads();
    s[0*NTHR+t] = acc[0]; s[1*NTHR+t] = acc[1];
    s[2*NTHR+t] = acc[2]; s[3*NTHR+t] = acc[3];
    __syncthreads();
    if (t >= 64) { m = 0; c = -1; return 0.f; }
    m = t >> 4; c = t & 15;
    float v = 0.f;
#pragma unroll
    for (int q = 0; q < KS; q++) v += s[m*NTHR + q*CW + c];
    return v;
}

// ------------------------- generic GEMM phase -------------------------
template<int M, int KL, bool RELU>
__device__ void gemm_phase(const float* const* rp, const float* __restrict__ W,
                           const float* __restrict__ bias, float* out, int N, float* s) {
    const int nch = N / CW;
    for (int ch = blockIdx.x; ch < nch; ch += NBLK) {
        int n0 = ch * CW;
        for (int t0 = 0; t0 < M; t0 += 4) {
            float acc[4];
            tile_dot4<KL>(rp, t0, W, N, n0 + (threadIdx.x & 15), acc);
            int m, c;
            float v = tile_reduce4(acc, s, m, c);
            if (c >= 0) {
                int n = n0 + c;
                v += __ldg(bias + n);
                if (RELU) v = fmaxf(v, 0.f);
                out[(t0 + m)*N + n] = v;
            }
        }
    }
}

// ------------------------- QKV phase -------------------------
template<int NC, int KL>
__device__ void qkv_phase(const Params& P, int l, int p0,
                          const float* const* rp, float* s) {
    constexpr int M = 4*NC;
    const int CPM = DM / CW;             // 40
    for (int ch = blockIdx.x; ch < 3*CPM; ch += NBLK) {
        int sel = ch / CPM;
        int n0 = (ch - sel*CPM) * CW;
        const float* W    = ((sel==0) ? P.Wq : (sel==1) ? P.Wk : P.Wv) + (long long)l*DM*DM;
        const float* bias = ((sel==0) ? P.bq : (sel==1) ? P.bk : P.bv) + l*DM;
        for (int t0 = 0; t0 < M; t0 += 4) {
            float acc[4];
            tile_dot4<KL>(rp, t0, W, DM, n0 + (threadIdx.x & 15), acc);
            int m, c;
            float v = tile_reduce4(acc, s, m, c);
            if (c >= 0) {
                int n = n0 + c;
                v += __ldg(bias + n);
                int mg = t0 + m;
                int b = mg / NC, jj = mg - b*NC, p = p0 + jj;
                if (sel == 0)      g_q[mg*DM + n] = v;
                else if (sel == 1) g_kc[((l*BB + b)*SSQ + p)*DM + n] = v;
                else               g_vc[((l*BB + b)*SSQ + p)*DM + n] = v;
            }
        }
    }
}

// ------------------------- LM head + argmax phase -------------------------
template<int KL>
__device__ void lm_phase(const Params& P, const float* const* rp, float* s,
                         unsigned long long* sk, int cl) {
    const int t = threadIdx.x;
    const int nch = VSZ / CW;            // 1875
    unsigned long long rb = 0ull;
    for (int ch = blockIdx.x; ch < nch; ch += NBLK) {
        int n0 = ch * CW;
        float acc[4];
        tile_dot4<KL>(rp, 0, P.lmW, VSZ, n0 + (t & 15), acc);
        int m, c;
        float v = tile_reduce4(acc, s, m, c);
        if (c >= 0) {
            int n = n0 + c;
            v += __ldg(P.lmb + n);
            unsigned u = __float_as_uint(v);
            u = (u & 0x80000000u) ? ~u : (u | 0x80000000u);
            unsigned long long key =
                ((unsigned long long)u << 32) | (unsigned)(0xFFFFFFFFu - (unsigned)n);
            if (key > rb) rb = key;       // thread's m (batch) fixed across chunks
        }
    }
    __syncthreads();
    if (t < 64) sk[t] = rb;
    __syncthreads();
    if (t < 4) {
        unsigned long long bb = sk[t*16];
        for (int i = 1; i < 16; i++) if (sk[t*16 + i] > bb) bb = sk[t*16 + i];
        if (bb) atomicMax(&g_bestA[cl][t], bb);
    }
    __syncthreads();
}

// ------------------------- attention phase -------------------------
template<int NC>
__device__ void attn_phase(int l, int p0) {
    const int wp = threadIdx.x >> 5, lane = threadIdx.x & 31;
    const int total = BB*NH*NC;
    for (int tup = blockIdx.x*NWP + wp; tup < total; tup += TOTW) {
        int b = tup / (NH*NC);
        int rem = tup - b*NH*NC;
        int h = rem / NC, j = rem - h*NC;
        int p = p0 + j, nk = p + 1;
        int r = b*NC + j;
        float* qp = g_q + r*DM + h*DHD;
        float sc = -1e30f;
        if (lane < nk) {
            float* kp = g_kc + ((l*BB + b)*SSQ + lane)*DM + h*DHD;
            float sv = 0.f;
#pragma unroll
            for (int d = 0; d < DHD; d++) sv = fmaf(qp[d], kp[d], sv);
            sc = sv / sqrtf((float)DHD);
        }
        float mx = sc;
        for (int o = 16; o > 0; o >>= 1) mx = fmaxf(mx, __shfl_xor_sync(0xffffffffu, mx, o));
        float e = (lane < nk) ? expf(sc - mx) : 0.f;
        float sum = e;
        for (int o = 16; o > 0; o >>= 1) sum += __shfl_xor_sync(0xffffffffu, sum, o);
        float o0 = 0.f, o1 = 0.f, o2 = 0.f;
        float* vb = g_vc + ((l*BB + b)*SSQ)*DM + h*DHD;
        for (int jk = 0; jk < nk; jk++) {
            float pj = __shfl_sync(0xffffffffu, e, jk) / sum;
            float* vp = vb + jk*DM;
            o0 = fmaf(pj, vp[lane],      o0);
            o1 = fmaf(pj, vp[lane + 32], o1);
            if (lane < 16) o2 = fmaf(pj, vp[lane + 64], o2);
        }
        float* ao = g_ao + r*DM + h*DHD;
        ao[lane] = o0; ao[lane + 32] = o1;
        if (lane < 16) ao[lane + 64] = o2;
    }
}

// ------------------------- LayerNorm -------------------------
__device__ __forceinline__ void ln_row_warp(const float* a, const float* r,
                                            const float* __restrict__ sc,
                                            const float* __restrict__ bi,
                                            float* dst) {
    int lane = threadIdx.x & 31;
    float v[20];
    float sum = 0.f;
#pragma unroll
    for (int i = 0; i < 20; i++) {
        float x = a[lane + 32*i] + r[lane + 32*i];
        v[i] = x; sum += x;
    }
#pragma unroll
    for (int o = 16; o > 0; o >>= 1) sum += __shfl_xor_sync(0xffffffffu, sum, o);
    float mean = sum / DM;
    float vs = 0.f;
#pragma unroll
    for (int i = 0; i < 20; i++) { float d = v[i] - mean; vs += d*d; }
#pragma unroll
    for (int o = 16; o > 0; o >>= 1) vs += __shfl_xor_sync(0xffffffffu, vs, o);
    float dn = sqrtf(vs / DM + 1e-6f);
#pragma unroll
    for (int i = 0; i < 20; i++)
        dst[lane + 32*i] = (v[i] - mean) / dn * __ldg(sc + lane + 32*i)
                           + __ldg(bi + lane + 32*i);
}

// decode: 4 warps recompute LN of 4 rows into smem; all threads sync after
__device__ __forceinline__ void ln4(const float* a, const float* r,
                                    const float* __restrict__ sc,
                                    const float* __restrict__ bi, float* sA) {
    int wp = threadIdx.x >> 5;
    if (wp < 4) ln_row_warp(a + wp*DM, r + wp*DM, sc, bi, sA + wp*DM);
    __syncthreads();
}

// prefill: global LN over M rows
template<int M>
__device__ void ln_phase(const float* a, const float* r,
                         const float* __restrict__ sc, const float* __restrict__ bi,
                         float* dst) {
    int gw = blockIdx.x*NWP + (threadIdx.x >> 5);
    for (int row = gw; row < M; row += TOTW)
        ln_row_warp(a + row*DM, r + row*DM, sc, bi, dst + row*DM);
}

// ------------------------- prefill (M=36, classic 7-phase) -------------------------
__device__ void prefill(const Params& P, unsigned &gen, Shr& S) {
    const int t = threadIdx.x;
    if (t < 36) {
        int b = t / 9, j = t - b*9;
        int tok = g_inp[b*SSQ + j];
        if (tok < 0 || tok >= VSZ) tok = 0;
        S.toks[t] = tok;
    }
    __syncthreads();
    // materialize g_h = emb rows (striped across blocks; read 4 gsyncs later)
    for (int r = blockIdx.x; r < 36; r += NBLK)
        for (int d = t; d < DM; d += NTHR)
            g_h[r*DM + d] = __ldg(P.emb + (long long)S.toks[r]*DM + d);

    for (int l = 0; l < NL; l++) {
        if (t < 36) S.rp[t] = (l == 0) ? (P.emb + (long long)S.toks[t]*DM)
                                       : (g_h + t*DM);
        __syncthreads();
        qkv_phase<9,20>(P, l, 0, S.rp, S.s);                                  gsync(gen);
        attn_phase<9>(l, 0);                                                  gsync(gen);
        if (t < 36) S.rp[t] = g_ao + t*DM;
        __syncthreads();
        gemm_phase<36,20,false>(S.rp, P.Wo + (long long)l*DM*DM,
                                P.bo + l*DM, g_r1, DM, S.s);                  gsync(gen);
        ln_phase<36>(g_h, g_r1, P.ln1s + l*DM, P.ln1b + l*DM, g_h2);          gsync(gen);
        if (t < 36) S.rp[t] = g_h2 + t*DM;
        __syncthreads();
        gemm_phase<36,20,true>(S.rp, P.W1 + (long long)l*DM*FFH,
                               P.b1 + l*FFH, g_f1, FFH, S.s);                 gsync(gen);
        if (t < 36) S.rp[t] = g_f1 + t*FFH;
        __syncthreads();
        gemm_phase<36,80,false>(S.rp, P.W2 + (long long)l*FFH*DM,
                                P.b2 + l*DM, g_r2, DM, S.s);                  gsync(gen);
        ln_phase<36>(g_h2, g_r2, P.ln2s + l*DM, P.ln2b + l*DM, g_h);          gsync(gen);
    }
    if (t < 4) S.rp[t] = g_h + (t*9 + 8)*DM;
    __syncthreads();
    lm_phase<20>(P, S.rp, S.s, S.sk, 8);                                      gsync(gen);
}

// ------------------------- one decode step (fused LN, 31 barriers) -------------------------
__device__ bool decode_step(int p, const Params& P, unsigned &gen, Shr& S) {
    const int t = threadIdx.x;
    if (t < 4) {
        unsigned long long k = g_bestA[p-1][t];
        S.toks[t] = (int)(0xFFFFFFFFu - (unsigned)(k & 0xFFFFFFFFu));
    }
    __syncthreads();
    if (blockIdx.x == 0 && t < 4) P.out[t*32 + (p-1)] = (float)S.toks[t];
    bool alleos = (S.toks[0] == EOS_TOK && S.toks[1] == EOS_TOK &&
                   S.toks[2] == EOS_TOK && S.toks[3] == EOS_TOK);
    if (alleos || p == 32) return false;

    // QKV l=0: stage emb rows in sA; block0 also materializes g_h (LN1 residual)
    for (int i = t; i < 4*DM; i += NTHR) {
        int r = i / DM, d = i - r*DM;
        float v = __ldg(P.emb + (long long)S.toks[r]*DM + d);
        S.sA[i] = v;
        if (blockIdx.x == 0) g_h[i] = v;
    }
    if (t < 4) S.rp[t] = S.sA + t*DM;
    __syncthreads();
    qkv_phase<1,20>(P, 0, p, S.rp, S.s);                                      gsync(gen);

    for (int l = 0; l < NL; l++) {
        attn_phase<1>(l, p);                                                  gsync(gen);
        if (t < 4) S.rp[t] = g_ao + t*DM;
        __syncthreads();
        gemm_phase<4,20,false>(S.rp, P.Wo + (long long)l*DM*DM,
                               P.bo + l*DM, g_r1, DM, S.s);                   gsync(gen);
        // FFN1: recompute LN1 into sA; block0 materializes g_h2
        ln4(g_h, g_r1, P.ln1s + l*DM, P.ln1b + l*DM, S.sA);
        if (blockIdx.x == 0)
            for (int i = t; i < 4*DM; i += NTHR) g_h2[i] = S.sA[i];
        if (t < 4) S.rp[t] = S.sA + t*DM;
        __syncthreads();
        gemm_phase<4,20,true>(S.rp, P.W1 + (long long)l*DM*FFH,
                              P.b1 + l*FFH, g_f1, FFH, S.s);                  gsync(gen);
        if (t < 4) S.rp[t] = g_f1 + t*FFH;
        __syncthreads();
        gemm_phase<4,80,false>(S.rp, P.W2 + (long long)l*FFH*DM,
                               P.b2 + l*DM, g_r2, DM, S.s);                   gsync(gen);
        if (l < NL-1) {
            // next-layer QKV: recompute LN2 into sA; block0 materializes g_h
            ln4(g_h2, g_r2, P.ln2s + l*DM, P.ln2b + l*DM, S.sA);
            if (blockIdx.x == 0)
                for (int i = t; i < 4*DM; i += NTHR) g_h[i] = S.sA[i];
            if (t < 4) S.rp[t] = S.sA + t*DM;
            __syncthreads();
            qkv_phase<1,20>(P, l+1, p, S.rp, S.s);                            gsync(gen);
        }
    }
    // LM: recompute final LN2 into sA
    ln4(g_h2, g_r2, P.ln2s + 5*DM, P.ln2b + 5*DM, S.sA);
    if (t < 4) S.rp[t] = S.sA + t*DM;
    __syncthreads();
    lm_phase<20>(P, S.rp, S.s, S.sk, p);                                      gsync(gen);
    return true;
}

// ------------------------- persistent mega-kernel -------------------------
__global__ __launch_bounds__(NTHR, 1)
void mega_kernel(Params P) {
    __shared__ Shr S;
    __shared__ unsigned sg;
    if (threadIdx.x == 0) sg = g_genv;
    __syncthreads();
    unsigned gen = sg;

    if (blockIdx.x == 0) {
        int t = threadIdx.x;
        if (t < BB*SSQ) g_inp[t] = 0;
        if (t < BB*32)  P.out[t] = 0.f;
        if (t < SSQ*BB) ((unsigned long long*)g_bestA)[t] = 0ull;
        __syncthreads();
        if (t < BB) g_inp[t*SSQ] = 1;
        if (t < 32) {
            int tok = P.words[t];
            g_inp[(t >> 3)*SSQ + 1 + (t & 7)] = tok;
            P.out[(t >> 3)*32 + (t & 7)] = (float)tok;
        }
    }
    gsync(gen);

    prefill(P, gen, S);
    for (int p = 9; p <= 32; p++)
        if (!decode_step(p, P, gen, S)) break;
}

// ------------------------- host -------------------------
extern "C" void kernel_launch(void* const* d_in, const int* in_sizes, int n_in,
                              void* d_out, int out_size) {
    (void)in_sizes; (void)out_size;
    int base = n_in - 19;
    Params P;
    P.words = (const int*)d_in[0];
    P.emb  = (const float*)d_in[base + 0];
    P.Wq   = (const float*)d_in[base + 1];
    P.bq   = (const float*)d_in[base + 2];
    P.Wk   = (const float*)d_in[base + 3];
    P.bk   = (const float*)d_in[base + 4];
    P.Wv   = (const float*)d_in[base + 5];
    P.bv   = (const float*)d_in[base + 6];
    P.Wo   = (const float*)d_in[base + 7];
    P.bo   = (const float*)d_in[base + 8];
    P.ln1s = (const float*)d_in[base + 9];
    P.ln1b = (const float*)d_in[base + 10];
    P.W1   = (const float*)d_in[base + 11];
    P.b1   = (const float*)d_in[base + 12];
    P.W2   = (const float*)d_in[base + 13];
    P.b2   = (const float*)d_in[base + 14];
    P.ln2s = (const float*)d_in[base + 15];
    P.ln2b = (const float*)d_in[base + 16];
    P.lmW  = (const float*)d_in[base + 17];
    P.lmb  = (const float*)d_in[base + 18];
    P.out  = (float*)d_out;

    mega_kernel<<<NBLK, NTHR>>>(P);
}